// round 4
// baseline (speedup 1.0000x reference)
#include <cuda_runtime.h>
#include <math.h>
#include <stdint.h>

#define HN   16384      // H*W per batch
#define CO   256
#define CIN  1024
#define CQ   32
#define NBAT 4

// ---------------- device scratch (no allocations allowed) ----------------
__device__ float g_x[NBAT*CO*HN];        // conv output, pre-BN     (64 MB)
__device__ float g_V[NBAT*CO*HN];        // V                       (64 MB)
__device__ float g_Q[NBAT*CQ*HN];        // Q (normalized in place) ( 8 MB)
__device__ float g_K[NBAT*CQ*HN];        // K (normalized in place) ( 8 MB)
__device__ float g_Wqkv[384*256];        // packed [wq;wk;wv;0-pad]
__device__ float g_bqkv[384];
__device__ float g_stats[512];           // per-channel sum / sumsq
__device__ float g_scale[256];
__device__ float g_shift[256];
__device__ float g_Ksum[NBAT*CQ];
__device__ float g_Vsum[NBAT*CO];
__device__ float g_matrix[NBAT*CQ*CO];   // Kn @ V^T

// ---------------- helpers ----------------
__device__ __forceinline__ uint32_t f2tf(float f){
    uint32_t r; asm("cvt.rna.tf32.f32 %0, %1;" : "=r"(r) : "f"(f)); return r;
}
__device__ __forceinline__ void mma8(float* c, const uint32_t* a, const uint32_t* b){
    asm volatile("mma.sync.aligned.m16n8k8.row.col.f32.tf32.tf32.f32 "
        "{%0,%1,%2,%3}, {%4,%5,%6,%7}, {%8,%9}, {%0,%1,%2,%3};"
        : "+f"(c[0]),"+f"(c[1]),"+f"(c[2]),"+f"(c[3])
        : "r"(a[0]),"r"(a[1]),"r"(a[2]),"r"(a[3]),"r"(b[0]),"r"(b[1]));
}

// ---------------- tiny prep kernels ----------------
__global__ void k_zero(){
    int i = blockIdx.x*256 + threadIdx.x;
    if (i < 512) g_stats[i] = 0.f;
    i -= 512;
    if (i >= 0 && i < NBAT*CQ*CO) g_matrix[i] = 0.f;
}

__global__ void k_prep(const float* __restrict__ wq, const float* __restrict__ bq,
                       const float* __restrict__ wk, const float* __restrict__ bk,
                       const float* __restrict__ wv, const float* __restrict__ bv){
    int r = blockIdx.x, k = threadIdx.x;
    float w;
    if      (r < 32)  w = wq[r*256 + k];
    else if (r < 64)  w = wk[(r-32)*256 + k];
    else if (r < 320) w = wv[(r-64)*256 + k];
    else              w = 0.f;
    g_Wqkv[r*256 + k] = w;
    if (k == 0){
        float bb = (r<32) ? bq[r] : (r<64) ? bk[r-32] : (r<320) ? bv[r-64] : 0.f;
        g_bqkv[r] = bb;
    }
}

// ---------------- conv GEMM: x = W[256,1024] * fcat[1024, 65536] ----------------
// TF32 mma, tile 128x128x16, 8 warps (2M x 4N), double-buffered smem.
__global__ __launch_bounds__(256) void k_conv(const float* __restrict__ s5, const float* __restrict__ s4,
                                              const float* __restrict__ s3, const float* __restrict__ s2,
                                              const float* __restrict__ W){
    __shared__ uint32_t As[2][16][132];
    __shared__ uint32_t Bs[2][16][132];
    const int tid = threadIdx.x;
    const int m0 = blockIdx.x*128;
    const int j0 = blockIdx.y*128;
    const int b  = j0 >> 14;
    const int n0 = j0 & (HN-1);
    const int warp = tid>>5, lane = tid&31;
    const int wm = (warp>>2)*64, wn = (warp&3)*32;
    const int gid = lane>>2, tig = lane&3;

    float acc[4][4][4];
    #pragma unroll
    for (int i=0;i<4;i++)
        #pragma unroll
        for (int j=0;j<4;j++)
            #pragma unroll
            for (int r=0;r<4;r++) acc[i][j][r]=0.f;

    float ar[8], br[8];

    auto loadA = [&](int k0){
        #pragma unroll
        for (int i=0;i<8;i++){ int idx=i*256+tid; int m=idx>>4, k=idx&15;
            ar[i] = W[(m0+m)*CIN + k0+k]; }
    };
    auto loadB = [&](int k0){
        const int t = k0>>8;
        const float* Sp = (t==0)?s5:(t==1)?s4:(t==2)?s3:s2;
        const int cb = k0 & 255;
        #pragma unroll
        for (int i=0;i<8;i++){ int idx=i*256+tid; int kk=idx>>7, n=idx&127;
            br[i] = Sp[((b<<8)+(cb+kk))*HN + n0+n]; }
    };
    auto stA = [&](int buf){
        #pragma unroll
        for (int i=0;i<8;i++){ int idx=i*256+tid; int m=idx>>4, k=idx&15;
            As[buf][k][m] = f2tf(ar[i]); }
    };
    auto stB = [&](int buf){
        #pragma unroll
        for (int i=0;i<8;i++){ int idx=i*256+tid; int kk=idx>>7, n=idx&127;
            Bs[buf][kk][n] = f2tf(br[i]); }
    };

    loadA(0); loadB(0); stA(0); stB(0);
    __syncthreads();
    const int KST = CIN/16;
    for (int kt=0; kt<KST; ++kt){
        int buf = kt & 1;
        if (kt+1 < KST){ loadA((kt+1)*16); loadB((kt+1)*16); }
        #pragma unroll
        for (int kk=0; kk<16; kk+=8){
            uint32_t af[4][4], bf[4][2];
            #pragma unroll
            for (int mi=0;mi<4;mi++){
                int m = wm + mi*16 + gid;
                af[mi][0]=As[buf][kk+tig  ][m];
                af[mi][1]=As[buf][kk+tig  ][m+8];
                af[mi][2]=As[buf][kk+tig+4][m];
                af[mi][3]=As[buf][kk+tig+4][m+8];
            }
            #pragma unroll
            for (int ni=0;ni<4;ni++){
                int n = wn + ni*8 + gid;
                bf[ni][0]=Bs[buf][kk+tig  ][n];
                bf[ni][1]=Bs[buf][kk+tig+4][n];
            }
            #pragma unroll
            for (int mi=0;mi<4;mi++)
                #pragma unroll
                for (int ni=0;ni<4;ni++)
                    mma8(acc[mi][ni], af[mi], bf[ni]);
        }
        if (kt+1 < KST){ stA(buf^1); stB(buf^1); __syncthreads(); }
    }

    #pragma unroll
    for (int mi=0;mi<4;mi++){
        #pragma unroll
        for (int h=0;h<2;h++){
            int mg = m0 + wm + mi*16 + gid + h*8;
            float* dst = g_x + ((b<<8)+mg)*HN + n0;
            #pragma unroll
            for (int ni=0;ni<4;ni++){
                int ng = wn + ni*8 + tig*2;
                float2 v; v.x = acc[mi][ni][h*2]; v.y = acc[mi][ni][h*2+1];
                *(float2*)(dst + ng) = v;
            }
        }
    }
}

// ---------------- BN statistics ----------------
__global__ __launch_bounds__(256) void k_stats(){
    __shared__ float r1[256], r2[256];
    int tid = threadIdx.x;
    int c = blockIdx.x >> 4; int seg = blockIdx.x & 15;
    int b = seg >> 2, ch = seg & 3;
    const float* src = g_x + ((b<<8)+c)*HN + ch*4096;
    float s=0.f, ss=0.f;
    #pragma unroll
    for (int i=0;i<16;i++){ float v = src[i*256+tid]; s += v; ss += v*v; }
    r1[tid]=s; r2[tid]=ss; __syncthreads();
    for (int st=128; st>0; st>>=1){
        if (tid<st){ r1[tid]+=r1[tid+st]; r2[tid]+=r2[tid+st]; }
        __syncthreads();
    }
    if (tid==0){ atomicAdd(&g_stats[c], r1[0]); atomicAdd(&g_stats[256+c], r2[0]); }
}

__global__ void k_bnfin(const float* __restrict__ bng, const float* __restrict__ bnb){
    int c = threadIdx.x;
    float s = g_stats[c], ss = g_stats[256+c];
    float mean = s * (1.f/65536.f);
    float var  = ss * (1.f/65536.f) - mean*mean;
    var = fmaxf(var, 0.f);
    float inv = 1.f / sqrtf(var + 1e-5f);
    float sc = bng[c] * inv;
    g_scale[c] = sc;
    g_shift[c] = bnb[c] - mean*sc;
}

// ---------------- QKV GEMM: [384,256] * feat(256, 65536), BN+ReLU on the fly ----------------
__global__ __launch_bounds__(256) void k_qkv(){
    __shared__ uint32_t As[2][16][132];
    __shared__ uint32_t Bs[2][16][132];
    __shared__ float sSc[256], sSh[256];
    const int tid = threadIdx.x;
    sSc[tid] = g_scale[tid]; sSh[tid] = g_shift[tid];
    __syncthreads();

    const int m0 = blockIdx.x*128;
    const int j0 = blockIdx.y*128;
    const int b  = j0 >> 14;
    const int n0 = j0 & (HN-1);
    const int warp = tid>>5, lane = tid&31;
    const int wm = (warp>>2)*64, wn = (warp&3)*32;
    const int gid = lane>>2, tig = lane&3;

    float acc[4][4][4];
    #pragma unroll
    for (int i=0;i<4;i++)
        #pragma unroll
        for (int j=0;j<4;j++)
            #pragma unroll
            for (int r=0;r<4;r++) acc[i][j][r]=0.f;

    float ar[8], br[8];
    auto loadA = [&](int k0){
        #pragma unroll
        for (int i=0;i<8;i++){ int idx=i*256+tid; int m=idx>>4, k=idx&15;
            ar[i] = g_Wqkv[(m0+m)*256 + k0+k]; }
    };
    auto loadB = [&](int k0){
        #pragma unroll
        for (int i=0;i<8;i++){ int idx=i*256+tid; int kk=idx>>7, n=idx&127;
            int k = k0 + kk;
            float v = g_x[((b<<8)+k)*HN + n0+n];
            br[i] = fmaxf(v*sSc[k] + sSh[k], 0.f); }
    };
    auto stA = [&](int buf){
        #pragma unroll
        for (int i=0;i<8;i++){ int idx=i*256+tid; int m=idx>>4, k=idx&15;
            As[buf][k][m] = f2tf(ar[i]); }
    };
    auto stB = [&](int buf){
        #pragma unroll
        for (int i=0;i<8;i++){ int idx=i*256+tid; int kk=idx>>7, n=idx&127;
            Bs[buf][kk][n] = f2tf(br[i]); }
    };

    loadA(0); loadB(0); stA(0); stB(0);
    __syncthreads();
    const int KST = 256/16;
    for (int kt=0; kt<KST; ++kt){
        int buf = kt & 1;
        if (kt+1 < KST){ loadA((kt+1)*16); loadB((kt+1)*16); }
        #pragma unroll
        for (int kk=0; kk<16; kk+=8){
            uint32_t af[4][4], bf[4][2];
            #pragma unroll
            for (int mi=0;mi<4;mi++){
                int m = wm + mi*16 + gid;
                af[mi][0]=As[buf][kk+tig  ][m];
                af[mi][1]=As[buf][kk+tig  ][m+8];
                af[mi][2]=As[buf][kk+tig+4][m];
                af[mi][3]=As[buf][kk+tig+4][m+8];
            }
            #pragma unroll
            for (int ni=0;ni<4;ni++){
                int n = wn + ni*8 + gid;
                bf[ni][0]=Bs[buf][kk+tig  ][n];
                bf[ni][1]=Bs[buf][kk+tig+4][n];
            }
            #pragma unroll
            for (int mi=0;mi<4;mi++)
                #pragma unroll
                for (int ni=0;ni<4;ni++)
                    mma8(acc[mi][ni], af[mi], bf[ni]);
        }
        if (kt+1 < KST){ stA(buf^1); stB(buf^1); __syncthreads(); }
    }

    #pragma unroll
    for (int mi=0;mi<4;mi++){
        #pragma unroll
        for (int h=0;h<2;h++){
            int mg = m0 + wm + mi*16 + gid + h*8;
            if (mg >= 320) continue;
            float bb = g_bqkv[mg];
            float* dst;
            if      (mg < 32) dst = g_Q + ((b<<5)+mg)*HN;
            else if (mg < 64) dst = g_K + ((b<<5)+(mg-32))*HN;
            else              dst = g_V + ((b<<8)+(mg-64))*HN;
            dst += n0;
            #pragma unroll
            for (int ni=0;ni<4;ni++){
                int ng = wn + ni*8 + tig*2;
                float2 v; v.x = acc[mi][ni][h*2] + bb; v.y = acc[mi][ni][h*2+1] + bb;
                *(float2*)(dst + ng) = v;
            }
        }
    }
}

// ---------------- L2-normalize Q, K in place (per position, over 32 channels) ----------------
__global__ __launch_bounds__(256) void k_norm(){
    int p = blockIdx.x*256 + threadIdx.x;
    int b = p >> 14, n = p & (HN-1);
    float qv[32], kv[32];
    float sq = 0.f, sk = 0.f;
    #pragma unroll
    for (int q=0;q<32;q++){ float v = g_Q[((b<<5)+q)*HN + n]; qv[q]=v; sq += v*v; }
    #pragma unroll
    for (int q=0;q<32;q++){ float v = g_K[((b<<5)+q)*HN + n]; kv[q]=v; sk += v*v; }
    float iq = 1.f / fmaxf(sqrtf(sq), 1e-6f);
    float ik = 1.f / fmaxf(sqrtf(sk), 1e-6f);
    #pragma unroll
    for (int q=0;q<32;q++){
        g_Q[((b<<5)+q)*HN + n] = qv[q]*iq;
        g_K[((b<<5)+q)*HN + n] = kv[q]*ik;
    }
}

// ---------------- row sums: Ksum[b][q], Vsum[b][c] ----------------
__global__ __launch_bounds__(256) void k_rowsum(){
    __shared__ float red[256];
    int r = blockIdx.x, tid = threadIdx.x;
    const float* src; float* dst;
    if (r < 128){ src = g_K + r*HN;        dst = &g_Ksum[r]; }
    else        { src = g_V + (r-128)*HN;  dst = &g_Vsum[r-128]; }
    float s = 0.f;
    #pragma unroll
    for (int i=0;i<64;i++) s += src[i*256+tid];
    red[tid]=s; __syncthreads();
    for (int st=128; st>0; st>>=1){
        if (tid<st) red[tid]+=red[tid+st];
        __syncthreads();
    }
    if (tid==0) *dst = red[0];
}

// ---------------- matrix[b][q][c] = sum_n Kn[q][n]*V[c][n] ----------------
__global__ __launch_bounds__(256) void k_matrix(){
    __shared__ float Ks[32][33];
    __shared__ float Vs[32][257];
    int tid = threadIdx.x;
    int b = blockIdx.x >> 7; int chunk = blockIdx.x & 127;   // 128 n per block
    int lane = tid & 31, wq_ = tid >> 5;
    float acc[4][8];
    #pragma unroll
    for (int a=0;a<4;a++)
        #pragma unroll
        for (int j=0;j<8;j++) acc[a][j]=0.f;

    for (int t=0;t<4;t++){
        int nt = chunk*128 + t*32;
        #pragma unroll
        for (int i=0;i<4;i++){ int q=i*8+wq_; Ks[q][lane] = g_K[((b<<5)+q)*HN + nt+lane]; }
        #pragma unroll
        for (int i=0;i<32;i++){ int c=i*8+wq_; Vs[lane][c] = g_V[((b<<8)+c)*HN + nt+lane]; }
        __syncthreads();
        #pragma unroll 4
        for (int n=0;n<32;n++){
            float kr[4];
            #pragma unroll
            for (int a=0;a<4;a++) kr[a] = Ks[wq_*4+a][n];
            #pragma unroll
            for (int j=0;j<8;j++){
                float v = Vs[n][lane + 32*j];
                #pragma unroll
                for (int a=0;a<4;a++) acc[a][j] += kr[a]*v;
            }
        }
        __syncthreads();
    }
    #pragma unroll
    for (int a=0;a<4;a++)
        #pragma unroll
        for (int j=0;j<8;j++){
            int q = wq_*4+a, c = lane + 32*j;
            atomicAdd(&g_matrix[(b<<13) + (q<<8) + c], acc[a][j]);
        }
}

// ---------------- final: out = nan_to_num(gamma*(Vsum + Qn^T M)*tailor) + relu(BN(x)) ----------------
__global__ __launch_bounds__(128) void k_final(const float* __restrict__ gamma_p, float* __restrict__ out){
    __shared__ __align__(16) float Ms[32*256];
    __shared__ __align__(16) float sV[256];
    __shared__ float sKs[32];
    __shared__ float sSc[256], sSh[256];
    int tid = threadIdx.x;
    int p = blockIdx.x*128 + tid;
    int b = p >> 14, n = p & (HN-1);

    #pragma unroll 8
    for (int i=0;i<64;i++) Ms[i*128+tid] = g_matrix[(b<<13) + i*128 + tid];
    #pragma unroll
    for (int i=0;i<2;i++){
        sV[i*128+tid]  = g_Vsum[(b<<8) + i*128 + tid];
        sSc[i*128+tid] = g_scale[i*128 + tid];
        sSh[i*128+tid] = g_shift[i*128 + tid];
    }
    if (tid < 32) sKs[tid] = g_Ksum[(b<<5) + tid];
    __syncthreads();

    float qr[32];
    float e = 0.f;
    #pragma unroll
    for (int q=0;q<32;q++){ qr[q] = g_Q[((b<<5)+q)*HN + n]; e += qr[q]*sKs[q]; }
    float tail = 1.f / fmaxf(16384.f + e, 1e-6f);
    float gm = *gamma_p;

    for (int c4=0;c4<64;c4++){
        float4 a = *(const float4*)&sV[c4*4];
        #pragma unroll
        for (int q=0;q<32;q++){
            float4 m4 = *(const float4*)&Ms[q*256 + c4*4];
            a.x += qr[q]*m4.x; a.y += qr[q]*m4.y; a.z += qr[q]*m4.z; a.w += qr[q]*m4.w;
        }
        #pragma unroll
        for (int j=0;j<4;j++){
            int c = c4*4 + j;
            float wv = ((float*)&a)[j] * tail;
            float o = gm * wv;
            if (isnan(o)) o = 0.f;
            else if (isinf(o)) o = (o > 0.f) ? 1.f : -1.f;
            int idx = ((b<<8)+c)*HN + n;
            float f = fmaxf(g_x[idx]*sSc[c] + sSh[c], 0.f);
            out[idx] = o + f;
        }
    }
}

// ---------------- launcher ----------------
extern "C" void kernel_launch(void* const* d_in, const int* in_sizes, int n_in,
                              void* d_out, int out_size){
    (void)in_sizes; (void)n_in; (void)out_size;
    const float* s5    = (const float*)d_in[0];
    const float* s4    = (const float*)d_in[1];
    const float* s3    = (const float*)d_in[2];
    const float* s2    = (const float*)d_in[3];
    const float* wconv = (const float*)d_in[4];
    const float* bng   = (const float*)d_in[5];
    const float* bnb   = (const float*)d_in[6];
    const float* wq    = (const float*)d_in[7];
    const float* bq    = (const float*)d_in[8];
    const float* wk    = (const float*)d_in[9];
    const float* bk    = (const float*)d_in[10];
    const float* wv    = (const float*)d_in[11];
    const float* bv    = (const float*)d_in[12];
    const float* gamma = (const float*)d_in[13];
    float* out = (float*)d_out;

    k_zero  <<<130, 256>>>();
    k_prep  <<<384, 256>>>(wq, bq, wk, bk, wv, bv);
    k_conv  <<<dim3(2, 512), 256>>>(s5, s4, s3, s2, wconv);
    k_stats <<<4096, 256>>>();
    k_bnfin <<<1, 256>>>(bng, bnb);
    k_qkv   <<<dim3(3, 512), 256>>>();
    k_norm  <<<256, 256>>>();
    k_rowsum<<<1152, 256>>>();
    k_matrix<<<512, 256>>>();
    k_final <<<512, 128>>>(gamma, out);
}

// round 6
// speedup vs baseline: 1.0122x; 1.0122x over previous
#include <cuda_runtime.h>
#include <math.h>
#include <stdint.h>

#define HN   16384      // H*W per batch
#define CO   256
#define CIN  1024
#define CQ   32
#define NBAT 4

// ---------------- device scratch (no allocations allowed) ----------------
__device__ float g_x[NBAT*CO*HN];        // conv output, pre-BN     (64 MB)
__device__ float g_V[NBAT*CO*HN];        // V                       (64 MB)
__device__ float g_Q[NBAT*CQ*HN];        // Q (normalized in place) ( 8 MB)
__device__ float g_K[NBAT*CQ*HN];        // K (normalized in place) ( 8 MB)
__device__ float g_Wqkv[384*256];        // packed [wq;wk;wv;0-pad]
__device__ float g_bqkv[384];
__device__ float g_stats[512];           // per-channel sum / sumsq
__device__ float g_scale[256];
__device__ float g_shift[256];
__device__ float g_Ksum[NBAT*CQ];
__device__ float g_Vsum[NBAT*CO];
__device__ float g_matrix[NBAT*CQ*CO];   // Kn @ V^T

// ---------------- helpers ----------------
__device__ __forceinline__ uint32_t f2tf(float f){
    uint32_t r; asm("cvt.rna.tf32.f32 %0, %1;" : "=r"(r) : "f"(f)); return r;
}
__device__ __forceinline__ void mma8(float* c, const uint32_t* a, const uint32_t* b){
    asm volatile("mma.sync.aligned.m16n8k8.row.col.f32.tf32.tf32.f32 "
        "{%0,%1,%2,%3}, {%4,%5,%6,%7}, {%8,%9}, {%0,%1,%2,%3};"
        : "+f"(c[0]),"+f"(c[1]),"+f"(c[2]),"+f"(c[3])
        : "r"(a[0]),"r"(a[1]),"r"(a[2]),"r"(a[3]),"r"(b[0]),"r"(b[1]));
}

// ---------------- tiny prep kernels ----------------
__global__ void k_zero(){
    int i = blockIdx.x*256 + threadIdx.x;
    if (i < 512) g_stats[i] = 0.f;
    i -= 512;
    if (i >= 0 && i < NBAT*CQ*CO) g_matrix[i] = 0.f;
}

__global__ void k_prep(const float* __restrict__ wq, const float* __restrict__ bq,
                       const float* __restrict__ wk, const float* __restrict__ bk,
                       const float* __restrict__ wv, const float* __restrict__ bv){
    int r = blockIdx.x, k = threadIdx.x;
    float w;
    if      (r < 32)  w = wq[r*256 + k];
    else if (r < 64)  w = wk[(r-32)*256 + k];
    else if (r < 320) w = wv[(r-64)*256 + k];
    else              w = 0.f;
    g_Wqkv[r*256 + k] = w;
    if (k == 0){
        float bb = (r<32) ? bq[r] : (r<64) ? bk[r-32] : (r<320) ? bv[r-64] : 0.f;
        g_bqkv[r] = bb;
    }
}

// ---------------- conv GEMM: x = W[256,1024] * fcat[1024, 65536] ----------------
// TF32 mma, tile 128x128x16, 8 warps (2M x 4N), double-buffered smem.
__global__ __launch_bounds__(256) void k_conv(const float* __restrict__ s5, const float* __restrict__ s4,
                                              const float* __restrict__ s3, const float* __restrict__ s2,
                                              const float* __restrict__ W){
    __shared__ uint32_t As[2][16][132];
    __shared__ uint32_t Bs[2][16][132];
    const int tid = threadIdx.x;
    const int m0 = blockIdx.x*128;
    const int j0 = blockIdx.y*128;
    const int b  = j0 >> 14;
    const int n0 = j0 & (HN-1);
    const int warp = tid>>5, lane = tid&31;
    const int wm = (warp>>2)*64, wn = (warp&3)*32;
    const int gid = lane>>2, tig = lane&3;

    float acc[4][4][4];
    #pragma unroll
    for (int i=0;i<4;i++)
        #pragma unroll
        for (int j=0;j<4;j++)
            #pragma unroll
            for (int r=0;r<4;r++) acc[i][j][r]=0.f;

    float ar[8], br[8];

    auto loadA = [&](int k0){
        #pragma unroll
        for (int i=0;i<8;i++){ int idx=i*256+tid; int m=idx>>4, k=idx&15;
            ar[i] = W[(m0+m)*CIN + k0+k]; }
    };
    auto loadB = [&](int k0){
        const int t = k0>>8;
        const float* Sp = (t==0)?s5:(t==1)?s4:(t==2)?s3:s2;
        const int cb = k0 & 255;
        #pragma unroll
        for (int i=0;i<8;i++){ int idx=i*256+tid; int kk=idx>>7, n=idx&127;
            br[i] = Sp[((b<<8)+(cb+kk))*HN + n0+n]; }
    };
    auto stA = [&](int buf){
        #pragma unroll
        for (int i=0;i<8;i++){ int idx=i*256+tid; int m=idx>>4, k=idx&15;
            As[buf][k][m] = f2tf(ar[i]); }
    };
    auto stB = [&](int buf){
        #pragma unroll
        for (int i=0;i<8;i++){ int idx=i*256+tid; int kk=idx>>7, n=idx&127;
            Bs[buf][kk][n] = f2tf(br[i]); }
    };

    loadA(0); loadB(0); stA(0); stB(0);
    __syncthreads();
    const int KST = CIN/16;
    for (int kt=0; kt<KST; ++kt){
        int buf = kt & 1;
        if (kt+1 < KST){ loadA((kt+1)*16); loadB((kt+1)*16); }
        #pragma unroll
        for (int kk=0; kk<16; kk+=8){
            uint32_t af[4][4], bf[4][2];
            #pragma unroll
            for (int mi=0;mi<4;mi++){
                int m = wm + mi*16 + gid;
                af[mi][0]=As[buf][kk+tig  ][m];
                af[mi][1]=As[buf][kk+tig  ][m+8];
                af[mi][2]=As[buf][kk+tig+4][m];
                af[mi][3]=As[buf][kk+tig+4][m+8];
            }
            #pragma unroll
            for (int ni=0;ni<4;ni++){
                int n = wn + ni*8 + gid;
                bf[ni][0]=Bs[buf][kk+tig  ][n];
                bf[ni][1]=Bs[buf][kk+tig+4][n];
            }
            #pragma unroll
            for (int mi=0;mi<4;mi++)
                #pragma unroll
                for (int ni=0;ni<4;ni++)
                    mma8(acc[mi][ni], af[mi], bf[ni]);
        }
        if (kt+1 < KST){ stA(buf^1); stB(buf^1); __syncthreads(); }
    }

    #pragma unroll
    for (int mi=0;mi<4;mi++){
        #pragma unroll
        for (int h=0;h<2;h++){
            int mg = m0 + wm + mi*16 + gid + h*8;
            float* dst = g_x + ((b<<8)+mg)*HN + n0;
            #pragma unroll
            for (int ni=0;ni<4;ni++){
                int ng = wn + ni*8 + tig*2;
                float2 v; v.x = acc[mi][ni][h*2]; v.y = acc[mi][ni][h*2+1];
                *(float2*)(dst + ng) = v;
            }
        }
    }
}

// ---------------- BN statistics ----------------
__global__ __launch_bounds__(256) void k_stats(){
    __shared__ float r1[256], r2[256];
    int tid = threadIdx.x;
    int c = blockIdx.x >> 4; int seg = blockIdx.x & 15;
    int b = seg >> 2, ch = seg & 3;
    const float* src = g_x + ((b<<8)+c)*HN + ch*4096;
    float s=0.f, ss=0.f;
    #pragma unroll
    for (int i=0;i<16;i++){ float v = src[i*256+tid]; s += v; ss += v*v; }
    r1[tid]=s; r2[tid]=ss; __syncthreads();
    for (int st=128; st>0; st>>=1){
        if (tid<st){ r1[tid]+=r1[tid+st]; r2[tid]+=r2[tid+st]; }
        __syncthreads();
    }
    if (tid==0){ atomicAdd(&g_stats[c], r1[0]); atomicAdd(&g_stats[256+c], r2[0]); }
}

__global__ void k_bnfin(const float* __restrict__ bng, const float* __restrict__ bnb){
    int c = threadIdx.x;
    float s = g_stats[c], ss = g_stats[256+c];
    float mean = s * (1.f/65536.f);
    float var  = ss * (1.f/65536.f) - mean*mean;
    var = fmaxf(var, 0.f);
    float inv = 1.f / sqrtf(var + 1e-5f);
    float sc = bng[c] * inv;
    g_scale[c] = sc;
    g_shift[c] = bnb[c] - mean*sc;
}

// ---------------- QKV GEMM: [384,256] * feat(256, 65536), BN+ReLU on the fly ----------------
__global__ __launch_bounds__(256) void k_qkv(){
    __shared__ uint32_t As[2][16][132];
    __shared__ uint32_t Bs[2][16][132];
    __shared__ float sSc[256], sSh[256];
    const int tid = threadIdx.x;
    sSc[tid] = g_scale[tid]; sSh[tid] = g_shift[tid];
    __syncthreads();

    const int m0 = blockIdx.x*128;
    const int j0 = blockIdx.y*128;
    const int b  = j0 >> 14;
    const int n0 = j0 & (HN-1);
    const int warp = tid>>5, lane = tid&31;
    const int wm = (warp>>2)*64, wn = (warp&3)*32;
    const int gid = lane>>2, tig = lane&3;

    float acc[4][4][4];
    #pragma unroll
    for (int i=0;i<4;i++)
        #pragma unroll
        for (int j=0;j<4;j++)
            #pragma unroll
            for (int r=0;r<4;r++) acc[i][j][r]=0.f;

    float ar[8], br[8];
    auto loadA = [&](int k0){
        #pragma unroll
        for (int i=0;i<8;i++){ int idx=i*256+tid; int m=idx>>4, k=idx&15;
            ar[i] = g_Wqkv[(m0+m)*256 + k0+k]; }
    };
    auto loadB = [&](int k0){
        #pragma unroll
        for (int i=0;i<8;i++){ int idx=i*256+tid; int kk=idx>>7, n=idx&127;
            int k = k0 + kk;
            float v = g_x[((b<<8)+k)*HN + n0+n];
            br[i] = fmaxf(v*sSc[k] + sSh[k], 0.f); }
    };
    auto stA = [&](int buf){
        #pragma unroll
        for (int i=0;i<8;i++){ int idx=i*256+tid; int m=idx>>4, k=idx&15;
            As[buf][k][m] = f2tf(ar[i]); }
    };
    auto stB = [&](int buf){
        #pragma unroll
        for (int i=0;i<8;i++){ int idx=i*256+tid; int kk=idx>>7, n=idx&127;
            Bs[buf][kk][n] = f2tf(br[i]); }
    };

    loadA(0); loadB(0); stA(0); stB(0);
    __syncthreads();
    const int KST = 256/16;
    for (int kt=0; kt<KST; ++kt){
        int buf = kt & 1;
        if (kt+1 < KST){ loadA((kt+1)*16); loadB((kt+1)*16); }
        #pragma unroll
        for (int kk=0; kk<16; kk+=8){
            uint32_t af[4][4], bf[4][2];
            #pragma unroll
            for (int mi=0;mi<4;mi++){
                int m = wm + mi*16 + gid;
                af[mi][0]=As[buf][kk+tig  ][m];
                af[mi][1]=As[buf][kk+tig  ][m+8];
                af[mi][2]=As[buf][kk+tig+4][m];
                af[mi][3]=As[buf][kk+tig+4][m+8];
            }
            #pragma unroll
            for (int ni=0;ni<4;ni++){
                int n = wn + ni*8 + gid;
                bf[ni][0]=Bs[buf][kk+tig  ][n];
                bf[ni][1]=Bs[buf][kk+tig+4][n];
            }
            #pragma unroll
            for (int mi=0;mi<4;mi++)
                #pragma unroll
                for (int ni=0;ni<4;ni++)
                    mma8(acc[mi][ni], af[mi], bf[ni]);
        }
        if (kt+1 < KST){ stA(buf^1); stB(buf^1); __syncthreads(); }
    }

    #pragma unroll
    for (int mi=0;mi<4;mi++){
        #pragma unroll
        for (int h=0;h<2;h++){
            int mg = m0 + wm + mi*16 + gid + h*8;
            if (mg >= 320) continue;
            float bb = g_bqkv[mg];
            float* dst;
            if      (mg < 32) dst = g_Q + ((b<<5)+mg)*HN;
            else if (mg < 64) dst = g_K + ((b<<5)+(mg-32))*HN;
            else              dst = g_V + ((b<<8)+(mg-64))*HN;
            dst += n0;
            #pragma unroll
            for (int ni=0;ni<4;ni++){
                int ng = wn + ni*8 + tig*2;
                float2 v; v.x = acc[mi][ni][h*2] + bb; v.y = acc[mi][ni][h*2+1] + bb;
                *(float2*)(dst + ng) = v;
            }
        }
    }
}

// ---------------- L2-normalize Q, K in place (per position, over 32 channels) ----------------
__global__ __launch_bounds__(256) void k_norm(){
    int p = blockIdx.x*256 + threadIdx.x;
    int b = p >> 14, n = p & (HN-1);
    float qv[32], kv[32];
    float sq = 0.f, sk = 0.f;
    #pragma unroll
    for (int q=0;q<32;q++){ float v = g_Q[((b<<5)+q)*HN + n]; qv[q]=v; sq += v*v; }
    #pragma unroll
    for (int q=0;q<32;q++){ float v = g_K[((b<<5)+q)*HN + n]; kv[q]=v; sk += v*v; }
    float iq = 1.f / fmaxf(sqrtf(sq), 1e-6f);
    float ik = 1.f / fmaxf(sqrtf(sk), 1e-6f);
    #pragma unroll
    for (int q=0;q<32;q++){
        g_Q[((b<<5)+q)*HN + n] = qv[q]*iq;
        g_K[((b<<5)+q)*HN + n] = kv[q]*ik;
    }
}

// ---------------- row sums: Ksum[b][q], Vsum[b][c] ----------------
__global__ __launch_bounds__(256) void k_rowsum(){
    __shared__ float red[256];
    int r = blockIdx.x, tid = threadIdx.x;
    const float* src; float* dst;
    if (r < 128){ src = g_K + r*HN;        dst = &g_Ksum[r]; }
    else        { src = g_V + (r-128)*HN;  dst = &g_Vsum[r-128]; }
    float s = 0.f;
    #pragma unroll
    for (int i=0;i<64;i++) s += src[i*256+tid];
    red[tid]=s; __syncthreads();
    for (int st=128; st>0; st>>=1){
        if (tid<st) red[tid]+=red[tid+st];
        __syncthreads();
    }
    if (tid==0) *dst = red[0];
}

// ---------------- matrix[b][q][c] = sum_n Kn[q][n]*V[c][n] ----------------
__global__ __launch_bounds__(256) void k_matrix(){
    __shared__ float Ks[32][33];
    __shared__ float Vs[32][257];
    int tid = threadIdx.x;
    int b = blockIdx.x >> 7; int chunk = blockIdx.x & 127;   // 128 n per block
    int lane = tid & 31, wq_ = tid >> 5;
    float acc[4][8];
    #pragma unroll
    for (int a=0;a<4;a++)
        #pragma unroll
        for (int j=0;j<8;j++) acc[a][j]=0.f;

    for (int t=0;t<4;t++){
        int nt = chunk*128 + t*32;
        #pragma unroll
        for (int i=0;i<4;i++){ int q=i*8+wq_; Ks[q][lane] = g_K[((b<<5)+q)*HN + nt+lane]; }
        #pragma unroll
        for (int i=0;i<32;i++){ int c=i*8+wq_; Vs[lane][c] = g_V[((b<<8)+c)*HN + nt+lane]; }
        __syncthreads();
        #pragma unroll 4
        for (int n=0;n<32;n++){
            float kr[4];
            #pragma unroll
            for (int a=0;a<4;a++) kr[a] = Ks[wq_*4+a][n];
            #pragma unroll
            for (int j=0;j<8;j++){
                float v = Vs[n][lane + 32*j];
                #pragma unroll
                for (int a=0;a<4;a++) acc[a][j] += kr[a]*v;
            }
        }
        __syncthreads();
    }
    #pragma unroll
    for (int a=0;a<4;a++)
        #pragma unroll
        for (int j=0;j<8;j++){
            int q = wq_*4+a, c = lane + 32*j;
            atomicAdd(&g_matrix[(b<<13) + (q<<8) + c], acc[a][j]);
        }
}

// ---------------- final: out = nan_to_num(gamma*(Vsum + Qn^T M)*tailor) + relu(BN(x)) ----------------
__global__ __launch_bounds__(128) void k_final(const float* __restrict__ gamma_p, float* __restrict__ out){
    __shared__ __align__(16) float Ms[32*256];
    __shared__ __align__(16) float sV[256];
    __shared__ float sKs[32];
    __shared__ float sSc[256], sSh[256];
    int tid = threadIdx.x;
    int p = blockIdx.x*128 + tid;
    int b = p >> 14, n = p & (HN-1);

    #pragma unroll 8
    for (int i=0;i<64;i++) Ms[i*128+tid] = g_matrix[(b<<13) + i*128 + tid];
    #pragma unroll
    for (int i=0;i<2;i++){
        sV[i*128+tid]  = g_Vsum[(b<<8) + i*128 + tid];
        sSc[i*128+tid] = g_scale[i*128 + tid];
        sSh[i*128+tid] = g_shift[i*128 + tid];
    }
    if (tid < 32) sKs[tid] = g_Ksum[(b<<5) + tid];
    __syncthreads();

    float qr[32];
    float e = 0.f;
    #pragma unroll
    for (int q=0;q<32;q++){ qr[q] = g_Q[((b<<5)+q)*HN + n]; e += qr[q]*sKs[q]; }
    float tail = 1.f / fmaxf(16384.f + e, 1e-6f);
    float gm = *gamma_p;

    for (int c4=0;c4<64;c4++){
        float4 a = *(const float4*)&sV[c4*4];
        #pragma unroll
        for (int q=0;q<32;q++){
            float4 m4 = *(const float4*)&Ms[q*256 + c4*4];
            a.x += qr[q]*m4.x; a.y += qr[q]*m4.y; a.z += qr[q]*m4.z; a.w += qr[q]*m4.w;
        }
        #pragma unroll
        for (int j=0;j<4;j++){
            int c = c4*4 + j;
            float wv = ((float*)&a)[j] * tail;
            float o = gm * wv;
            if (isnan(o)) o = 0.f;
            else if (isinf(o)) o = (o > 0.f) ? 1.f : -1.f;
            int idx = ((b<<8)+c)*HN + n;
            float f = fmaxf(g_x[idx]*sSc[c] + sSh[c], 0.f);
            out[idx] = o + f;
        }
    }
}

// ---------------- launcher ----------------
extern "C" void kernel_launch(void* const* d_in, const int* in_sizes, int n_in,
                              void* d_out, int out_size){
    (void)in_sizes; (void)n_in; (void)out_size;
    const float* s5    = (const float*)d_in[0];
    const float* s4    = (const float*)d_in[1];
    const float* s3    = (const float*)d_in[2];
    const float* s2    = (const float*)d_in[3];
    const float* wconv = (const float*)d_in[4];
    const float* bng   = (const float*)d_in[5];
    const float* bnb   = (const float*)d_in[6];
    const float* wq    = (const float*)d_in[7];
    const float* bq    = (const float*)d_in[8];
    const float* wk    = (const float*)d_in[9];
    const float* bk    = (const float*)d_in[10];
    const float* wv    = (const float*)d_in[11];
    const float* bv    = (const float*)d_in[12];
    const float* gamma = (const float*)d_in[13];
    float* out = (float*)d_out;

    k_zero  <<<130, 256>>>();
    k_prep  <<<384, 256>>>(wq, bq, wk, bk, wv, bv);
    k_conv  <<<dim3(2, 512), 256>>>(s5, s4, s3, s2, wconv);
    k_stats <<<4096, 256>>>();
    k_bnfin <<<1, 256>>>(bng, bnb);
    k_qkv   <<<dim3(3, 512), 256>>>();
    k_norm  <<<256, 256>>>();
    k_rowsum<<<1152, 256>>>();
    k_matrix<<<512, 256>>>();
    k_final <<<512, 128>>>(gamma, out);
}